// round 2
// baseline (speedup 1.0000x reference)
#include <cuda_runtime.h>
#include <cstdint>

#define FDIM   1024
#define FV     256          // float4 per row
#define DDOM   8
#define MAXN   16384
#define MAXNA  (MAXN / 256)          // 64 count blocks
#define MAXSCHED (MAXN / 64 + DDOM)  // 264 schedule entries
#define EPSV   1e-5f

// ---------------- scratch (__device__ globals; zero-initialized) ----------------
__device__ unsigned char g_ydom[MAXN];          // domain per row (0..7)
__device__ int   g_bc[MAXNA * DDOM];            // per-block domain counts
__device__ int   g_off[MAXNA * DDOM];           // global write offset per block/domain
__device__ int   g_perm[MAXN];                  // row indices sorted by domain (stable)
__device__ int   g_dcnt[DDOM];                  // total count per domain
__device__ int4  g_sched[MAXSCHED];             // {domain, perm_start, nrows, 0}
__device__ float g_P[MAXSCHED * FDIM];          // per-entry partial sum(x)
__device__ float g_Q[MAXSCHED * FDIM];          // per-entry partial sum(x*x)
__device__ float g_A[DDOM * FDIM];              // gamma*inv
__device__ float g_B[DDOM * FDIM];              // beta - mean*gamma*inv

// int64-vs-int32 y detection (odd 32-bit words all zero over 32 values)
__device__ __forceinline__ int detect64(const int* __restrict__ y) {
    const int4* p = (const int4*)y;
    int acc = 0;
#pragma unroll
    for (int i = 0; i < 8; i++) { int4 a = p[i]; acc |= a.y | a.w; }
    return acc == 0;
}

// ---------------- kernel A: per-block domain counts + domain bytes ----------------
__global__ __launch_bounds__(256)
void domcnt_k(const int* __restrict__ yi, int n) {
    __shared__ int wc[8][DDOM];
    const int tid = threadIdx.x;
    const int row = blockIdx.x * 256 + tid;
    if (tid < 64) ((int*)wc)[tid] = 0;
    const int is64 = detect64(yi);
    int d = DDOM;   // invalid bucket for OOB rows
    if (row < n) {
        d = is64 ? yi[2 * row] : yi[row];
        g_ydom[row] = (unsigned char)d;
    }
    __syncthreads();
    unsigned m = __match_any_sync(0xffffffffu, d);
    const int lane = tid & 31, w = tid >> 5;
    if (d < DDOM && (int)(__ffs(m) - 1) == lane) wc[w][d] = __popc(m);
    __syncthreads();
    if (tid < DDOM) {
        int s = 0;
#pragma unroll
        for (int ww = 0; ww < 8; ww++) s += wc[ww][tid];
        g_bc[blockIdx.x * DDOM + tid] = s;
    }
}

// ---------------- kernel B: scans + schedule build (1 block) ----------------
__global__ __launch_bounds__(256)
void sched_k(int n, int nA, int nsched) {
    __shared__ int sbc[MAXNA * DDOM], soff[MAXNA * DDOM];
    __shared__ int sdt[DDOM], sdstart[DDOM + 1], sebase[DDOM + 1];
    const int tid = threadIdx.x;
    for (int i = tid; i < nA * DDOM; i += 256) sbc[i] = g_bc[i];
    __syncthreads();
    if (tid < DDOM) {
        int t = 0;
        for (int b = 0; b < nA; b++) { soff[b * DDOM + tid] = t; t += sbc[b * DDOM + tid]; }
        sdt[tid] = t;
    }
    __syncthreads();
    if (tid == 0) {
        int s = 0, e = 0;
        for (int d = 0; d < DDOM; d++) {
            sdstart[d] = s; sebase[d] = e;
            s += sdt[d]; e += (sdt[d] + 63) >> 6;
        }
        sdstart[DDOM] = s; sebase[DDOM] = e;
    }
    __syncthreads();
    for (int i = tid; i < nA * DDOM; i += 256)
        g_off[i] = sdstart[i & 7] + soff[i];
    for (int e = tid; e < nsched; e += 256) {
        int dd = -1, k = 0;
#pragma unroll
        for (int d = 0; d < DDOM; d++)
            if (e >= sebase[d] && e < sebase[d + 1]) { dd = d; k = e - sebase[d]; }
        int4 s;
        if (dd >= 0) {
            int p0 = sdstart[dd] + k * 64;
            int nr = min(64, sdt[dd] - k * 64);
            s = make_int4(dd, p0, nr, 0);
        } else {
            s = make_int4(-1, 0, 0, 0);
        }
        g_sched[e] = s;
    }
    if (tid < DDOM) g_dcnt[tid] = sdt[tid];
}

// ---------------- kernel C: stable scatter of row indices ----------------
__global__ __launch_bounds__(256)
void perm_k(int n) {
    __shared__ int wc[8][DDOM], wcp[8][DDOM];
    const int tid = threadIdx.x;
    const int row = blockIdx.x * 256 + tid;
    if (tid < 64) ((int*)wc)[tid] = 0;
    int d = DDOM;
    if (row < n) d = (int)g_ydom[row];
    __syncthreads();
    unsigned m = __match_any_sync(0xffffffffu, d);
    const int lane = tid & 31, w = tid >> 5;
    const int rank = __popc(m & ((1u << lane) - 1u));
    if (d < DDOM && (int)(__ffs(m) - 1) == lane) wc[w][d] = __popc(m);
    __syncthreads();
    if (tid < DDOM) {
        int run = 0;
#pragma unroll
        for (int ww = 0; ww < 8; ww++) { wcp[ww][tid] = run; run += wc[ww][tid]; }
    }
    __syncthreads();
    if (d < DDOM) {
        int pos = g_off[blockIdx.x * DDOM + d] + wcp[w][d] + rank;
        g_perm[pos] = row;
    }
}

// ---------------- pass1: single-domain streaming sums ----------------
__global__ __launch_bounds__(256)
void pass1_k(const float4* __restrict__ x4) {
    __shared__ int srow[64];
    __shared__ int4 ss;
    const int tid = threadIdx.x;
    if (tid == 0) ss = g_sched[blockIdx.x];
    __syncthreads();
    const int d = ss.x, p0 = ss.y, nr = ss.z;
    if (d < 0) return;
    if (tid < nr) srow[tid] = g_perm[p0 + tid];
    __syncthreads();

    float4 s1 = make_float4(0.f, 0.f, 0.f, 0.f);
    float4 s2 = make_float4(0.f, 0.f, 0.f, 0.f);
    int i = 0;
    for (; i + 8 <= nr; i += 8) {
        float4 v[8];
#pragma unroll
        for (int j = 0; j < 8; j++)
            v[j] = __ldcg(x4 + (size_t)srow[i + j] * FV + tid);
#pragma unroll
        for (int j = 0; j < 8; j++) {
            s1.x += v[j].x; s1.y += v[j].y; s1.z += v[j].z; s1.w += v[j].w;
            s2.x = fmaf(v[j].x, v[j].x, s2.x);
            s2.y = fmaf(v[j].y, v[j].y, s2.y);
            s2.z = fmaf(v[j].z, v[j].z, s2.z);
            s2.w = fmaf(v[j].w, v[j].w, s2.w);
        }
    }
    for (; i < nr; i++) {
        float4 v = __ldcg(x4 + (size_t)srow[i] * FV + tid);
        s1.x += v.x; s1.y += v.y; s1.z += v.z; s1.w += v.w;
        s2.x = fmaf(v.x, v.x, s2.x);
        s2.y = fmaf(v.y, v.y, s2.y);
        s2.z = fmaf(v.z, v.z, s2.z);
        s2.w = fmaf(v.w, v.w, s2.w);
    }
    const size_t o = (size_t)blockIdx.x * FV + tid;
    ((float4*)g_P)[o] = s1;
    ((float4*)g_Q)[o] = s2;
}

// ---------------- reduce: fold tagged segments -> A/B tables ----------------
__global__ __launch_bounds__(256)
void reduce_k(const float* __restrict__ gamma, const float* __restrict__ beta, int nsched) {
    __shared__ int stag[MAXSCHED];
    const int tid = threadIdx.x;
    const int o = blockIdx.x * 256 + tid;
    const int d = o >> 10, f = o & 1023;
    for (int i = tid; i < nsched; i += 256) stag[i] = g_sched[i].x;
    __syncthreads();

    float a0 = 0.f, a1 = 0.f, q0 = 0.f, q1 = 0.f;
    int b = 0;
    for (; b + 2 <= nsched; b += 2) {
        float m0 = (stag[b] == d) ? 1.f : 0.f;
        float m1 = (stag[b + 1] == d) ? 1.f : 0.f;
        float p0 = g_P[b * FDIM + f], p1 = g_P[(b + 1) * FDIM + f];
        float r0 = g_Q[b * FDIM + f], r1 = g_Q[(b + 1) * FDIM + f];
        a0 = fmaf(m0, p0, a0); a1 = fmaf(m1, p1, a1);
        q0 = fmaf(m0, r0, q0); q1 = fmaf(m1, r1, q1);
    }
    for (; b < nsched; b++) {
        float m0 = (stag[b] == d) ? 1.f : 0.f;
        a0 = fmaf(m0, g_P[b * FDIM + f], a0);
        q0 = fmaf(m0, g_Q[b * FDIM + f], q0);
    }
    const float s1 = a0 + a1, s2 = q0 + q1;
    const float c = (float)g_dcnt[d];

    float A, Bv;
    if (c > 1.5f) {
        float mean = s1 / c;
        float var  = s2 / c - mean * mean;
        float inv  = rsqrtf(var + EPSV);
        A  = gamma[o] * inv;
        Bv = fmaf(-mean, A, beta[o]);
    } else if (c > 0.5f) { A = 1.f; Bv = 0.f; }   // single-sample: out = x
    else                 { A = 0.f; Bv = 0.f; }   // empty: unused
    g_A[o] = A;
    g_B[o] = Bv;
}

// ---------------- pass2: out = A[d]*x + B[d], single-domain blocks ----------------
__global__ __launch_bounds__(256)
void pass2_k(const float4* __restrict__ x4, float4* __restrict__ o4) {
    __shared__ int srow[16];
    __shared__ int4 ss;
    const int e = blockIdx.x >> 2, sl = blockIdx.x & 3;
    const int tid = threadIdx.x;
    if (tid == 0) ss = g_sched[e];
    __syncthreads();
    const int d = ss.x;
    const int base = sl * 16;
    const int nr = min(16, ss.z - base);
    if (d < 0 || nr <= 0) return;
    if (tid < nr) srow[tid] = g_perm[ss.y + base + tid];
    __syncthreads();

    const float4 a  = __ldg((const float4*)g_A + d * FV + tid);
    const float4 bb = __ldg((const float4*)g_B + d * FV + tid);

    int i = 0;
    for (; i + 4 <= nr; i += 4) {
        int r0 = srow[i], r1 = srow[i + 1], r2 = srow[i + 2], r3 = srow[i + 3];
        float4 v0 = __ldcg(x4 + (size_t)r0 * FV + tid);
        float4 v1 = __ldcg(x4 + (size_t)r1 * FV + tid);
        float4 v2 = __ldcg(x4 + (size_t)r2 * FV + tid);
        float4 v3 = __ldcg(x4 + (size_t)r3 * FV + tid);
        float4 w0, w1, w2, w3;
        w0.x = fmaf(v0.x, a.x, bb.x); w0.y = fmaf(v0.y, a.y, bb.y);
        w0.z = fmaf(v0.z, a.z, bb.z); w0.w = fmaf(v0.w, a.w, bb.w);
        w1.x = fmaf(v1.x, a.x, bb.x); w1.y = fmaf(v1.y, a.y, bb.y);
        w1.z = fmaf(v1.z, a.z, bb.z); w1.w = fmaf(v1.w, a.w, bb.w);
        w2.x = fmaf(v2.x, a.x, bb.x); w2.y = fmaf(v2.y, a.y, bb.y);
        w2.z = fmaf(v2.z, a.z, bb.z); w2.w = fmaf(v2.w, a.w, bb.w);
        w3.x = fmaf(v3.x, a.x, bb.x); w3.y = fmaf(v3.y, a.y, bb.y);
        w3.z = fmaf(v3.z, a.z, bb.z); w3.w = fmaf(v3.w, a.w, bb.w);
        o4[(size_t)r0 * FV + tid] = w0;
        o4[(size_t)r1 * FV + tid] = w1;
        o4[(size_t)r2 * FV + tid] = w2;
        o4[(size_t)r3 * FV + tid] = w3;
    }
    for (; i < nr; i++) {
        int r = srow[i];
        float4 v = __ldcg(x4 + (size_t)r * FV + tid);
        float4 w;
        w.x = fmaf(v.x, a.x, bb.x); w.y = fmaf(v.y, a.y, bb.y);
        w.z = fmaf(v.z, a.z, bb.z); w.w = fmaf(v.w, a.w, bb.w);
        o4[(size_t)r * FV + tid] = w;
    }
}

extern "C" void kernel_launch(void* const* d_in, const int* in_sizes, int n_in,
                              void* d_out, int out_size) {
    const float* x     = (const float*)d_in[0];
    const int*   y     = (const int*)d_in[1];
    const float* gamma = (const float*)d_in[2];
    const float* beta  = (const float*)d_in[3];
    float* out = (float*)d_out;

    const int n      = in_sizes[1];
    const int nA     = (n + 255) / 256;
    const int nsched = (n + 63) / 64 + DDOM;

    domcnt_k<<<nA, 256>>>(y, n);
    sched_k<<<1, 256>>>(n, nA, nsched);
    perm_k<<<nA, 256>>>(n);
    pass1_k<<<nsched, 256>>>((const float4*)x);
    reduce_k<<<(DDOM * FDIM) / 256, 256>>>(gamma, beta, nsched);
    pass2_k<<<nsched * 4, 256>>>((const float4*)x, (float4*)out);
}

// round 3
// speedup vs baseline: 1.3677x; 1.3677x over previous
#include <cuda_runtime.h>
#include <cstdint>

#define FDIM   1024
#define FV     256            // float4 per row
#define DDOM   8
#define RS     32             // rows per stats block
#define MAXSEG 512            // max stats blocks (16384/32)
#define RA     8              // rows per apply block
#define EPSV   1e-5f

// ---------------- scratch ----------------
__device__ float g_P[MAXSEG * DDOM * FDIM];   // partial sum(x)   per (seg, d)
__device__ float g_Q[MAXSEG * DDOM * FDIM];   // partial sum(x*x) per (seg, d)
__device__ int   g_c[MAXSEG * DDOM];          // per-seg domain counts
__device__ float g_A[DDOM * FDIM];            // gamma * inv
__device__ float g_B[DDOM * FDIM];            // beta - mean * gamma * inv

// int64-vs-int32 y detection (odd 32-bit words all zero over 32 values;
// false-positive prob for int32 data in 0..7 is 8^-16)
__device__ __forceinline__ int detect64(const int* __restrict__ y) {
    const int4* p = (const int4*)y;
    int acc = 0;
#pragma unroll
    for (int i = 0; i < 8; i++) { int4 a = p[i]; acc |= a.y | a.w; }
    return acc == 0;
}

#define ACCUM(v)                                  \
    s1.x += v.x; s1.y += v.y; s1.z += v.z; s1.w += v.w; \
    s2.x = fmaf(v.x, v.x, s2.x);                  \
    s2.y = fmaf(v.y, v.y, s2.y);                  \
    s2.z = fmaf(v.z, v.z, s2.z);                  \
    s2.w = fmaf(v.w, v.w, s2.w);

// ---------------- K1: stats with block-local domain grouping ----------------
__global__ __launch_bounds__(256)
void stats_k(const float4* __restrict__ x4, const int* __restrict__ yi, int n) {
    __shared__ int lst[DDOM][RS];
    __shared__ int cnt[DDOM];
    const int tid = threadIdx.x;
    const int r0  = blockIdx.x * RS;

    if (tid < DDOM) cnt[tid] = 0;
    __syncthreads();

    if (tid < 32) {                       // warp 0: deterministic local sort
        const int is64 = detect64(yi);
        const int r = r0 + tid;
        int d = -1;
        if (r < n) d = is64 ? yi[2 * r] : yi[r];
        unsigned m = __match_any_sync(0xffffffffu, d);
        int rank = __popc(m & ((1u << tid) - 1u));
        if (d >= 0) {
            lst[d][rank] = r;
            if (rank == 0) cnt[d] = __popc(m);
        }
    }
    __syncthreads();

#pragma unroll
    for (int d = 0; d < DDOM; d++) {
        const int nd = cnt[d];
        float4 s1 = make_float4(0.f, 0.f, 0.f, 0.f);
        float4 s2 = make_float4(0.f, 0.f, 0.f, 0.f);
        int i = 0;
        for (; i + 4 <= nd; i += 4) {
            float4 v0 = __ldcg(x4 + (size_t)lst[d][i]     * FV + tid);
            float4 v1 = __ldcg(x4 + (size_t)lst[d][i + 1] * FV + tid);
            float4 v2 = __ldcg(x4 + (size_t)lst[d][i + 2] * FV + tid);
            float4 v3 = __ldcg(x4 + (size_t)lst[d][i + 3] * FV + tid);
            ACCUM(v0); ACCUM(v1); ACCUM(v2); ACCUM(v3);
        }
        for (; i < nd; i++) {
            float4 v = __ldcg(x4 + (size_t)lst[d][i] * FV + tid);
            ACCUM(v);
        }
        const size_t o = ((size_t)blockIdx.x * DDOM + d) * FV + tid;
        ((float4*)g_P)[o] = s1;
        ((float4*)g_Q)[o] = s2;
        if (tid == 0) g_c[blockIdx.x * DDOM + d] = nd;
    }
}

// ---------------- K2: fold segments -> A/B tables ----------------
// grid = 128 blocks: block b handles domain d = b>>4, f4 positions
// [ (b&15)*16 , +16 ). 16 lanes per position sum NB/16 segments each.
__global__ __launch_bounds__(256)
void finalize_k(const float* __restrict__ gamma, const float* __restrict__ beta,
                int nb) {
    __shared__ float4 sp[16][16];   // [pos][lane] partial P
    __shared__ float4 sq[16][16];   // [pos][lane] partial Q
    __shared__ int    scnt[256];

    const int tid  = threadIdx.x;
    const int d    = blockIdx.x >> 4;
    const int pos0 = (blockIdx.x & 15) * 16;
    const int lane = tid & 15;
    const int pos  = tid >> 4;             // 0..15
    const int posIdx = pos0 + pos;         // f4 index within domain (0..255)

    // domain count: sum g_c[s*8+d] over all segments
    {
        int c = 0;
        for (int s = tid; s < nb; s += 256) c += g_c[s * DDOM + d];
        scnt[tid] = c;
    }
    __syncthreads();
    for (int off = 128; off > 0; off >>= 1) {
        if (tid < off) scnt[tid] += scnt[tid + off];
        __syncthreads();
    }
    const float c = (float)scnt[0];

    // lane-partial segment sums (L2-resident, MLP via independent P/Q streams)
    const float4* P4 = (const float4*)g_P;
    const float4* Q4 = (const float4*)g_Q;
    float4 ap = make_float4(0.f, 0.f, 0.f, 0.f);
    float4 aq = make_float4(0.f, 0.f, 0.f, 0.f);
    for (int s = lane; s < nb; s += 16) {
        const size_t o = ((size_t)s * DDOM + d) * FV + posIdx;
        float4 p = P4[o], q = Q4[o];
        ap.x += p.x; ap.y += p.y; ap.z += p.z; ap.w += p.w;
        aq.x += q.x; aq.y += q.y; aq.z += q.z; aq.w += q.w;
    }
    sp[pos][lane] = ap;
    sq[pos][lane] = aq;
    __syncthreads();

    if (lane == 0) {
        float4 s1 = sp[pos][0], s2 = sq[pos][0];
#pragma unroll
        for (int l = 1; l < 16; l++) {
            float4 p = sp[pos][l], q = sq[pos][l];
            s1.x += p.x; s1.y += p.y; s1.z += p.z; s1.w += p.w;
            s2.x += q.x; s2.y += q.y; s2.z += q.z; s2.w += q.w;
        }
        const int o = d * FDIM + posIdx * 4;
        float4 A, Bv;
        if (c > 1.5f) {
            const float rc = 1.0f / c;
            float4 g = *(const float4*)(gamma + o);
            float4 be = *(const float4*)(beta + o);
            float mx = s1.x * rc, my = s1.y * rc, mz = s1.z * rc, mw = s1.w * rc;
            float vx = fmaf(-mx, mx, s2.x * rc);
            float vy = fmaf(-my, my, s2.y * rc);
            float vz = fmaf(-mz, mz, s2.z * rc);
            float vw = fmaf(-mw, mw, s2.w * rc);
            A.x = g.x * rsqrtf(vx + EPSV);
            A.y = g.y * rsqrtf(vy + EPSV);
            A.z = g.z * rsqrtf(vz + EPSV);
            A.w = g.w * rsqrtf(vw + EPSV);
            Bv.x = fmaf(-mx, A.x, be.x);
            Bv.y = fmaf(-my, A.y, be.y);
            Bv.z = fmaf(-mz, A.z, be.z);
            Bv.w = fmaf(-mw, A.w, be.w);
        } else if (c > 0.5f) {   // single-sample domain: out = x
            A = make_float4(1.f, 1.f, 1.f, 1.f);
            Bv = make_float4(0.f, 0.f, 0.f, 0.f);
        } else {                 // empty domain (unused)
            A = make_float4(0.f, 0.f, 0.f, 0.f);
            Bv = make_float4(0.f, 0.f, 0.f, 0.f);
        }
        *(float4*)(g_A + o) = A;
        *(float4*)(g_B + o) = Bv;
    }
}

// ---------------- K3: out = A[d]*x + B[d] ----------------
__global__ __launch_bounds__(256)
void apply_k(const float4* __restrict__ x4, const int* __restrict__ yi,
             float4* __restrict__ o4, int n) {
    __shared__ int sd[RA];
    const int tid = threadIdx.x;
    const int r0  = blockIdx.x * RA;

    if (tid < RA) {
        const int is64 = detect64(yi);
        const int r = r0 + tid;
        sd[tid] = (r < n) ? (is64 ? yi[2 * r] : yi[r]) : 0;
    }
    __syncthreads();

    const float4* A4 = (const float4*)g_A;
    const float4* B4 = (const float4*)g_B;

#pragma unroll
    for (int j = 0; j < RA; j += 4) {
        const int r = r0 + j;
        if (r + 3 < n) {
            const int d0 = sd[j], d1 = sd[j + 1], d2 = sd[j + 2], d3 = sd[j + 3];
            const float4* p = x4 + (size_t)r * FV + tid;
            float4 v0 = __ldcg(p);
            float4 v1 = __ldcg(p + FV);
            float4 v2 = __ldcg(p + 2 * FV);
            float4 v3 = __ldcg(p + 3 * FV);
            float4 a0 = __ldg(A4 + d0 * FV + tid);
            float4 b0 = __ldg(B4 + d0 * FV + tid);
            float4 a1 = __ldg(A4 + d1 * FV + tid);
            float4 b1 = __ldg(B4 + d1 * FV + tid);
            float4 a2 = __ldg(A4 + d2 * FV + tid);
            float4 b2 = __ldg(B4 + d2 * FV + tid);
            float4 a3 = __ldg(A4 + d3 * FV + tid);
            float4 b3 = __ldg(B4 + d3 * FV + tid);
            float4 w0, w1, w2, w3;
            w0.x = fmaf(v0.x, a0.x, b0.x); w0.y = fmaf(v0.y, a0.y, b0.y);
            w0.z = fmaf(v0.z, a0.z, b0.z); w0.w = fmaf(v0.w, a0.w, b0.w);
            w1.x = fmaf(v1.x, a1.x, b1.x); w1.y = fmaf(v1.y, a1.y, b1.y);
            w1.z = fmaf(v1.z, a1.z, b1.z); w1.w = fmaf(v1.w, a1.w, b1.w);
            w2.x = fmaf(v2.x, a2.x, b2.x); w2.y = fmaf(v2.y, a2.y, b2.y);
            w2.z = fmaf(v2.z, a2.z, b2.z); w2.w = fmaf(v2.w, a2.w, b2.w);
            w3.x = fmaf(v3.x, a3.x, b3.x); w3.y = fmaf(v3.y, a3.y, b3.y);
            w3.z = fmaf(v3.z, a3.z, b3.z); w3.w = fmaf(v3.w, a3.w, b3.w);
            float4* q = o4 + (size_t)r * FV + tid;
            q[0]      = w0;
            q[FV]     = w1;
            q[2 * FV] = w2;
            q[3 * FV] = w3;
        } else {
            for (int k = 0; k < 4; k++) {
                const int rr = r + k;
                if (rr >= n) break;
                const int dd = sd[j + k];
                float4 v = __ldcg(x4 + (size_t)rr * FV + tid);
                float4 a = __ldg(A4 + dd * FV + tid);
                float4 b = __ldg(B4 + dd * FV + tid);
                float4 w;
                w.x = fmaf(v.x, a.x, b.x); w.y = fmaf(v.y, a.y, b.y);
                w.z = fmaf(v.z, a.z, b.z); w.w = fmaf(v.w, a.w, b.w);
                o4[(size_t)rr * FV + tid] = w;
            }
        }
    }
}

extern "C" void kernel_launch(void* const* d_in, const int* in_sizes, int n_in,
                              void* d_out, int out_size) {
    const float* x     = (const float*)d_in[0];
    const int*   y     = (const int*)d_in[1];
    const float* gamma = (const float*)d_in[2];
    const float* beta  = (const float*)d_in[3];
    float* out = (float*)d_out;

    const int n  = in_sizes[1];
    const int nb = (n + RS - 1) / RS;           // stats segments (512)

    stats_k<<<nb, 256>>>((const float4*)x, y, n);
    finalize_k<<<DDOM * 16, 256>>>(gamma, beta, nb);
    apply_k<<<(n + RA - 1) / RA, 256>>>((const float4*)x, y, (float4*)out, n);
}

// round 4
// speedup vs baseline: 1.4013x; 1.0245x over previous
#include <cuda_runtime.h>
#include <cstdint>

#define FDIM   1024
#define FV     256            // float4 per row
#define DDOM   8
#define MAXN   16384
#define MAXSEG 256            // stats blocks (16384 / 64)
#define RA     8              // rows per apply block
#define EPSV   1e-5f

// ---------------- scratch ----------------
__device__ float g_P[MAXSEG * DDOM * FDIM];   // partial sum(x)   per (seg, d)
__device__ float g_Q[MAXSEG * DDOM * FDIM];   // partial sum(x*x) per (seg, d)
__device__ int   g_c[MAXSEG * DDOM];          // per-seg domain counts
__device__ unsigned char g_ydom[MAXN];        // decoded domain per row
__device__ float g_A[DDOM * FDIM];            // gamma * inv
__device__ float g_B[DDOM * FDIM];            // beta - mean * gamma * inv

// int64-vs-int32 y detection (odd 32-bit words all zero over 32 values)
__device__ __forceinline__ int detect64(const int* __restrict__ y) {
    const int4* p = (const int4*)y;
    int acc = 0;
#pragma unroll
    for (int i = 0; i < 8; i++) { int4 a = p[i]; acc |= a.y | a.w; }
    return acc == 0;
}

#define ACCD(d, v)                                                    \
    S1[d].x += v.x; S1[d].y += v.y; S1[d].z += v.z; S1[d].w += v.w;   \
    S2[d].x = fmaf(v.x, v.x, S2[d].x);                                \
    S2[d].y = fmaf(v.y, v.y, S2[d].y);                                \
    S2[d].z = fmaf(v.z, v.z, S2[d].z);                                \
    S2[d].w = fmaf(v.w, v.w, S2[d].w);

// ---------------- K1: stats, 64 rows/block, 2 sorted tiles, reg accumulators ----
__global__ __launch_bounds__(256)
void stats_k(const float4* __restrict__ x4, const int* __restrict__ yi, int n) {
    __shared__ int lst[DDOM][32];     // prescaled row offsets (row * FV)
    __shared__ int scnt[DDOM];        // per-tile counts
    __shared__ int ccnt[DDOM];        // per-block counts
    const int tid = threadIdx.x;
    const int base = blockIdx.x * 64;

    float4 S1[DDOM], S2[DDOM];
#pragma unroll
    for (int d = 0; d < DDOM; d++) {
        S1[d] = make_float4(0.f, 0.f, 0.f, 0.f);
        S2[d] = make_float4(0.f, 0.f, 0.f, 0.f);
    }
    if (tid < DDOM) ccnt[tid] = 0;

    const int is64 = detect64(yi);

#pragma unroll
    for (int t = 0; t < 2; t++) {
        const int r0 = base + t * 32;
        __syncthreads();
        if (tid < DDOM) scnt[tid] = 0;
        __syncthreads();
        if (tid < 32) {                       // warp 0: deterministic local sort
            const int r = r0 + tid;
            int d = -1;
            if (r < n) d = is64 ? yi[2 * r] : yi[r];
            unsigned m = __match_any_sync(0xffffffffu, d);
            int rank = __popc(m & ((1u << tid) - 1u));
            if (d >= 0) {
                g_ydom[r] = (unsigned char)d;
                lst[d][rank] = r * FV;
                if (rank == 0) scnt[d] = __popc(m);
            }
        }
        __syncthreads();
#pragma unroll
        for (int d = 0; d < DDOM; d++) {
            const int nd = scnt[d];
            int i = 0;
            for (; i + 4 <= nd; i += 4) {
                float4 v0 = __ldcg(x4 + lst[d][i]     + tid);
                float4 v1 = __ldcg(x4 + lst[d][i + 1] + tid);
                float4 v2 = __ldcg(x4 + lst[d][i + 2] + tid);
                float4 v3 = __ldcg(x4 + lst[d][i + 3] + tid);
                ACCD(d, v0); ACCD(d, v1); ACCD(d, v2); ACCD(d, v3);
            }
            for (; i < nd; i++) {
                float4 v = __ldcg(x4 + lst[d][i] + tid);
                ACCD(d, v);
            }
        }
        if (tid < DDOM) ccnt[tid] += scnt[tid];
    }

#pragma unroll
    for (int d = 0; d < DDOM; d++) {
        const size_t o = ((size_t)blockIdx.x * DDOM + d) * FV + tid;
        ((float4*)g_P)[o] = S1[d];
        ((float4*)g_Q)[o] = S2[d];
    }
    if (tid < DDOM) g_c[blockIdx.x * DDOM + tid] = ccnt[tid];
}

// ---------------- K2: fold segments -> A/B tables ----------------
// grid = 8*32 = 256 blocks. Block: domain d = bIdx>>5, f4 positions
// (bIdx&31)*8 + warp. Each warp reduces one f4 position over all segs.
__global__ __launch_bounds__(256)
void finalize_k(const float* __restrict__ gamma, const float* __restrict__ beta,
                int nseg) {
    __shared__ int scnt[256];
    const int tid  = threadIdx.x;
    const int d    = blockIdx.x >> 5;
    const int w    = tid >> 5, lane = tid & 31;
    const int posIdx = (blockIdx.x & 31) * 8 + w;   // f4 index 0..255

    // domain count
    {
        int c = 0;
        for (int s = tid; s < nseg; s += 256) c += g_c[s * DDOM + d];
        scnt[tid] = c;
    }
    __syncthreads();
    for (int off = 128; off > 0; off >>= 1) {
        if (tid < off) scnt[tid] += scnt[tid + off];
        __syncthreads();
    }
    const float c = (float)scnt[0];

    const float4* P4 = (const float4*)g_P;
    const float4* Q4 = (const float4*)g_Q;
    float4 ap = make_float4(0.f, 0.f, 0.f, 0.f);
    float4 aq = make_float4(0.f, 0.f, 0.f, 0.f);
    for (int s = lane; s < nseg; s += 32) {
        const size_t o = ((size_t)s * DDOM + d) * FV + posIdx;
        float4 p = P4[o], q = Q4[o];
        ap.x += p.x; ap.y += p.y; ap.z += p.z; ap.w += p.w;
        aq.x += q.x; aq.y += q.y; aq.z += q.z; aq.w += q.w;
    }
#pragma unroll
    for (int off = 16; off > 0; off >>= 1) {
        ap.x += __shfl_down_sync(0xffffffffu, ap.x, off);
        ap.y += __shfl_down_sync(0xffffffffu, ap.y, off);
        ap.z += __shfl_down_sync(0xffffffffu, ap.z, off);
        ap.w += __shfl_down_sync(0xffffffffu, ap.w, off);
        aq.x += __shfl_down_sync(0xffffffffu, aq.x, off);
        aq.y += __shfl_down_sync(0xffffffffu, aq.y, off);
        aq.z += __shfl_down_sync(0xffffffffu, aq.z, off);
        aq.w += __shfl_down_sync(0xffffffffu, aq.w, off);
    }

    if (lane == 0) {
        const int o = d * FDIM + posIdx * 4;
        float4 A, Bv;
        if (c > 1.5f) {
            const float rc = 1.0f / c;
            float4 g  = *(const float4*)(gamma + o);
            float4 be = *(const float4*)(beta + o);
            float mx = ap.x * rc, my = ap.y * rc, mz = ap.z * rc, mw = ap.w * rc;
            float vx = fmaf(-mx, mx, aq.x * rc);
            float vy = fmaf(-my, my, aq.y * rc);
            float vz = fmaf(-mz, mz, aq.z * rc);
            float vw = fmaf(-mw, mw, aq.w * rc);
            A.x = g.x * rsqrtf(vx + EPSV);
            A.y = g.y * rsqrtf(vy + EPSV);
            A.z = g.z * rsqrtf(vz + EPSV);
            A.w = g.w * rsqrtf(vw + EPSV);
            Bv.x = fmaf(-mx, A.x, be.x);
            Bv.y = fmaf(-my, A.y, be.y);
            Bv.z = fmaf(-mz, A.z, be.z);
            Bv.w = fmaf(-mw, A.w, be.w);
        } else if (c > 0.5f) {   // single-sample domain: out = x
            A  = make_float4(1.f, 1.f, 1.f, 1.f);
            Bv = make_float4(0.f, 0.f, 0.f, 0.f);
        } else {                 // empty domain (unused)
            A  = make_float4(0.f, 0.f, 0.f, 0.f);
            Bv = make_float4(0.f, 0.f, 0.f, 0.f);
        }
        *(float4*)(g_A + o) = A;
        *(float4*)(g_B + o) = Bv;
    }
}

// ---------------- K3: out = A[d]*x + B[d] ----------------
__global__ __launch_bounds__(256)
void apply_k(const float4* __restrict__ x4, float4* __restrict__ o4, int n) {
    __shared__ int sd[RA];
    const int tid = threadIdx.x;
    const int r0  = blockIdx.x * RA;

    if (tid < RA) {
        const int r = r0 + tid;
        sd[tid] = (r < n) ? (int)g_ydom[r] : 0;
    }
    __syncthreads();

    const float4* A4 = (const float4*)g_A;
    const float4* B4 = (const float4*)g_B;

#pragma unroll
    for (int j = 0; j < RA; j += 4) {
        const int r = r0 + j;
        if (r + 3 < n) {
            const int d0 = sd[j], d1 = sd[j + 1], d2 = sd[j + 2], d3 = sd[j + 3];
            const float4* p = x4 + (size_t)r * FV + tid;
            float4 v0 = __ldcg(p);
            float4 v1 = __ldcg(p + FV);
            float4 v2 = __ldcg(p + 2 * FV);
            float4 v3 = __ldcg(p + 3 * FV);
            float4 a0 = __ldg(A4 + d0 * FV + tid);
            float4 b0 = __ldg(B4 + d0 * FV + tid);
            float4 a1 = __ldg(A4 + d1 * FV + tid);
            float4 b1 = __ldg(B4 + d1 * FV + tid);
            float4 a2 = __ldg(A4 + d2 * FV + tid);
            float4 b2 = __ldg(B4 + d2 * FV + tid);
            float4 a3 = __ldg(A4 + d3 * FV + tid);
            float4 b3 = __ldg(B4 + d3 * FV + tid);
            float4 w0, w1, w2, w3;
            w0.x = fmaf(v0.x, a0.x, b0.x); w0.y = fmaf(v0.y, a0.y, b0.y);
            w0.z = fmaf(v0.z, a0.z, b0.z); w0.w = fmaf(v0.w, a0.w, b0.w);
            w1.x = fmaf(v1.x, a1.x, b1.x); w1.y = fmaf(v1.y, a1.y, b1.y);
            w1.z = fmaf(v1.z, a1.z, b1.z); w1.w = fmaf(v1.w, a1.w, b1.w);
            w2.x = fmaf(v2.x, a2.x, b2.x); w2.y = fmaf(v2.y, a2.y, b2.y);
            w2.z = fmaf(v2.z, a2.z, b2.z); w2.w = fmaf(v2.w, a2.w, b2.w);
            w3.x = fmaf(v3.x, a3.x, b3.x); w3.y = fmaf(v3.y, a3.y, b3.y);
            w3.z = fmaf(v3.z, a3.z, b3.z); w3.w = fmaf(v3.w, a3.w, b3.w);
            float4* q = o4 + (size_t)r * FV + tid;
            __stcs(q,          w0);
            __stcs(q + FV,     w1);
            __stcs(q + 2 * FV, w2);
            __stcs(q + 3 * FV, w3);
        } else {
            for (int k = 0; k < 4; k++) {
                const int rr = r + k;
                if (rr >= n) break;
                const int dd = sd[j + k];
                float4 v = __ldcg(x4 + (size_t)rr * FV + tid);
                float4 a = __ldg(A4 + dd * FV + tid);
                float4 b = __ldg(B4 + dd * FV + tid);
                float4 w;
                w.x = fmaf(v.x, a.x, b.x); w.y = fmaf(v.y, a.y, b.y);
                w.z = fmaf(v.z, a.z, b.z); w.w = fmaf(v.w, a.w, b.w);
                __stcs(o4 + (size_t)rr * FV + tid, w);
            }
        }
    }
}

extern "C" void kernel_launch(void* const* d_in, const int* in_sizes, int n_in,
                              void* d_out, int out_size) {
    const float* x     = (const float*)d_in[0];
    const int*   y     = (const int*)d_in[1];
    const float* gamma = (const float*)d_in[2];
    const float* beta  = (const float*)d_in[3];
    float* out = (float*)d_out;

    const int n    = in_sizes[1];
    const int nseg = (n + 63) / 64;             // 256

    stats_k<<<nseg, 256>>>((const float4*)x, y, n);
    finalize_k<<<DDOM * 32, 256>>>(gamma, beta, nseg);
    apply_k<<<(n + RA - 1) / RA, 256>>>((const float4*)x, (float4*)out, n);
}

// round 5
// speedup vs baseline: 1.5818x; 1.1289x over previous
#include <cuda_runtime.h>
#include <cstdint>

#define FDIM   1024
#define FV     256            // float4 per row
#define DDOM   8
#define MAXN   16384
#define RSB    64             // rows per stats block
#define MAXSEG (MAXN / RSB)   // 256 stats blocks
#define RA     8              // rows per apply block
#define EPSV   1e-5f

// ---------------- scratch ----------------
__device__ float g_P[MAXSEG * DDOM * FDIM];   // partial sum(x)   per (seg, d)
__device__ float g_Q[MAXSEG * DDOM * FDIM];   // partial sum(x*x) per (seg, d)
__device__ int   g_c[MAXSEG * DDOM];          // per-seg domain counts
__device__ unsigned char g_ydom[MAXN];        // decoded domain per row
__device__ float g_A[DDOM * FDIM];            // gamma * inv
__device__ float g_B[DDOM * FDIM];            // beta - mean * gamma * inv

// int64-vs-int32 y detection (odd 32-bit words all zero over 32 values)
__device__ __forceinline__ int detect64(const int* __restrict__ y) {
    const int4* p = (const int4*)y;
    int acc = 0;
#pragma unroll
    for (int i = 0; i < 8; i++) { int4 a = p[i]; acc |= a.y | a.w; }
    return acc == 0;
}

#define ACCUM(v)                                        \
    s1.x += v.x; s1.y += v.y; s1.z += v.z; s1.w += v.w; \
    s2.x = fmaf(v.x, v.x, s2.x);                        \
    s2.y = fmaf(v.y, v.y, s2.y);                        \
    s2.z = fmaf(v.z, v.z, s2.z);                        \
    s2.w = fmaf(v.w, v.w, s2.w);

// ---------------- K1: stats, 64 rows/block, concat-sorted, 1 acc pair ------
__global__ __launch_bounds__(256, 4)
void stats_k(const float4* __restrict__ x4, const int* __restrict__ yi, int n) {
    __shared__ int lst[DDOM][RSB];    // prescaled row offsets (row * FV)
    __shared__ int cnt[DDOM];
    const int tid  = threadIdx.x;
    const int base = blockIdx.x * RSB;

    if (tid < DDOM) cnt[tid] = 0;
    __syncthreads();

    if (tid < 32) {
        const int is64 = detect64(yi);
        // tile 0
        {
            const int r = base + tid;
            int d = -1;
            if (r < n) d = is64 ? yi[2 * r] : yi[r];
            unsigned m = __match_any_sync(0xffffffffu, d);
            int rank = __popc(m & ((1u << tid) - 1u));
            if (d >= 0) {
                g_ydom[r] = (unsigned char)d;
                lst[d][rank] = r * FV;
                if (rank == 0) cnt[d] = __popc(m);
            }
        }
        __syncwarp();
        // tile 1 (append after tile-0 counts)
        {
            const int r = base + 32 + tid;
            int d = -1;
            if (r < n) d = is64 ? yi[2 * r] : yi[r];
            unsigned m = __match_any_sync(0xffffffffu, d);
            int rank = __popc(m & ((1u << tid) - 1u));
            int off = (d >= 0) ? cnt[d] : 0;   // all lanes read before leaders write
            __syncwarp();
            if (d >= 0) {
                g_ydom[r] = (unsigned char)d;
                lst[d][off + rank] = r * FV;
                if (rank == 0) cnt[d] = off + __popc(m);
            }
        }
    }
    __syncthreads();

#pragma unroll
    for (int d = 0; d < DDOM; d++) {
        const int nd = cnt[d];
        float4 s1 = make_float4(0.f, 0.f, 0.f, 0.f);
        float4 s2 = make_float4(0.f, 0.f, 0.f, 0.f);
        int i = 0;
        for (; i + 8 <= nd; i += 8) {
            float4 v0 = __ldcg(x4 + lst[d][i]     + tid);
            float4 v1 = __ldcg(x4 + lst[d][i + 1] + tid);
            float4 v2 = __ldcg(x4 + lst[d][i + 2] + tid);
            float4 v3 = __ldcg(x4 + lst[d][i + 3] + tid);
            float4 v4 = __ldcg(x4 + lst[d][i + 4] + tid);
            float4 v5 = __ldcg(x4 + lst[d][i + 5] + tid);
            float4 v6 = __ldcg(x4 + lst[d][i + 6] + tid);
            float4 v7 = __ldcg(x4 + lst[d][i + 7] + tid);
            ACCUM(v0); ACCUM(v1); ACCUM(v2); ACCUM(v3);
            ACCUM(v4); ACCUM(v5); ACCUM(v6); ACCUM(v7);
        }
        if (i + 4 <= nd) {
            float4 v0 = __ldcg(x4 + lst[d][i]     + tid);
            float4 v1 = __ldcg(x4 + lst[d][i + 1] + tid);
            float4 v2 = __ldcg(x4 + lst[d][i + 2] + tid);
            float4 v3 = __ldcg(x4 + lst[d][i + 3] + tid);
            ACCUM(v0); ACCUM(v1); ACCUM(v2); ACCUM(v3);
            i += 4;
        }
        for (; i < nd; i++) {
            float4 v = __ldcg(x4 + lst[d][i] + tid);
            ACCUM(v);
        }
        const size_t o = ((size_t)blockIdx.x * DDOM + d) * FV + tid;
        ((float4*)g_P)[o] = s1;
        ((float4*)g_Q)[o] = s2;
    }
    if (tid < DDOM) g_c[blockIdx.x * DDOM + tid] = cnt[tid];
}

// ---------------- K2: fold segments -> A/B tables ----------------
// grid = 8*32 = 256 blocks: domain d = bIdx>>5; warp w reduces f4 position
// (bIdx&31)*8 + w over all segments (lane-strided).
__global__ __launch_bounds__(256)
void finalize_k(const float* __restrict__ gamma, const float* __restrict__ beta,
                int nseg) {
    __shared__ int scnt[256];
    const int tid  = threadIdx.x;
    const int d    = blockIdx.x >> 5;
    const int w    = tid >> 5, lane = tid & 31;
    const int posIdx = (blockIdx.x & 31) * 8 + w;   // f4 index 0..255

    {
        int c = 0;
        for (int s = tid; s < nseg; s += 256) c += g_c[s * DDOM + d];
        scnt[tid] = c;
    }
    __syncthreads();
    for (int off = 128; off > 0; off >>= 1) {
        if (tid < off) scnt[tid] += scnt[tid + off];
        __syncthreads();
    }
    const float c = (float)scnt[0];

    const float4* P4 = (const float4*)g_P;
    const float4* Q4 = (const float4*)g_Q;
    float4 ap = make_float4(0.f, 0.f, 0.f, 0.f);
    float4 aq = make_float4(0.f, 0.f, 0.f, 0.f);
    for (int s = lane; s < nseg; s += 32) {
        const size_t o = ((size_t)s * DDOM + d) * FV + posIdx;
        float4 p = P4[o], q = Q4[o];
        ap.x += p.x; ap.y += p.y; ap.z += p.z; ap.w += p.w;
        aq.x += q.x; aq.y += q.y; aq.z += q.z; aq.w += q.w;
    }
#pragma unroll
    for (int off = 16; off > 0; off >>= 1) {
        ap.x += __shfl_down_sync(0xffffffffu, ap.x, off);
        ap.y += __shfl_down_sync(0xffffffffu, ap.y, off);
        ap.z += __shfl_down_sync(0xffffffffu, ap.z, off);
        ap.w += __shfl_down_sync(0xffffffffu, ap.w, off);
        aq.x += __shfl_down_sync(0xffffffffu, aq.x, off);
        aq.y += __shfl_down_sync(0xffffffffu, aq.y, off);
        aq.z += __shfl_down_sync(0xffffffffu, aq.z, off);
        aq.w += __shfl_down_sync(0xffffffffu, aq.w, off);
    }

    if (lane == 0) {
        const int o = d * FDIM + posIdx * 4;
        float4 A, Bv;
        if (c > 1.5f) {
            const float rc = 1.0f / c;
            float4 g  = *(const float4*)(gamma + o);
            float4 be = *(const float4*)(beta + o);
            float mx = ap.x * rc, my = ap.y * rc, mz = ap.z * rc, mw = ap.w * rc;
            float vx = fmaf(-mx, mx, aq.x * rc);
            float vy = fmaf(-my, my, aq.y * rc);
            float vz = fmaf(-mz, mz, aq.z * rc);
            float vw = fmaf(-mw, mw, aq.w * rc);
            A.x = g.x * rsqrtf(vx + EPSV);
            A.y = g.y * rsqrtf(vy + EPSV);
            A.z = g.z * rsqrtf(vz + EPSV);
            A.w = g.w * rsqrtf(vw + EPSV);
            Bv.x = fmaf(-mx, A.x, be.x);
            Bv.y = fmaf(-my, A.y, be.y);
            Bv.z = fmaf(-mz, A.z, be.z);
            Bv.w = fmaf(-mw, A.w, be.w);
        } else if (c > 0.5f) {   // single-sample domain: out = x
            A  = make_float4(1.f, 1.f, 1.f, 1.f);
            Bv = make_float4(0.f, 0.f, 0.f, 0.f);
        } else {                 // empty domain (unused)
            A  = make_float4(0.f, 0.f, 0.f, 0.f);
            Bv = make_float4(0.f, 0.f, 0.f, 0.f);
        }
        *(float4*)(g_A + o) = A;
        *(float4*)(g_B + o) = Bv;
    }
}

// ---------------- K3: out = A[d]*x + B[d] ----------------
__global__ __launch_bounds__(256)
void apply_k(const float4* __restrict__ x4, float4* __restrict__ o4, int n) {
    __shared__ int sd[RA];
    const int tid = threadIdx.x;
    const int r0  = blockIdx.x * RA;

    if (tid < RA) {
        const int r = r0 + tid;
        sd[tid] = (r < n) ? (int)g_ydom[r] : 0;
    }
    __syncthreads();

    const float4* A4 = (const float4*)g_A;
    const float4* B4 = (const float4*)g_B;

#pragma unroll
    for (int j = 0; j < RA; j += 4) {
        const int r = r0 + j;
        if (r + 3 < n) {
            const int d0 = sd[j], d1 = sd[j + 1], d2 = sd[j + 2], d3 = sd[j + 3];
            const float4* p = x4 + (size_t)r * FV + tid;
            float4 v0 = __ldcs(p);
            float4 v1 = __ldcs(p + FV);
            float4 v2 = __ldcs(p + 2 * FV);
            float4 v3 = __ldcs(p + 3 * FV);
            float4 a0 = __ldg(A4 + d0 * FV + tid);
            float4 b0 = __ldg(B4 + d0 * FV + tid);
            float4 a1 = __ldg(A4 + d1 * FV + tid);
            float4 b1 = __ldg(B4 + d1 * FV + tid);
            float4 a2 = __ldg(A4 + d2 * FV + tid);
            float4 b2 = __ldg(B4 + d2 * FV + tid);
            float4 a3 = __ldg(A4 + d3 * FV + tid);
            float4 b3 = __ldg(B4 + d3 * FV + tid);
            float4 w0, w1, w2, w3;
            w0.x = fmaf(v0.x, a0.x, b0.x); w0.y = fmaf(v0.y, a0.y, b0.y);
            w0.z = fmaf(v0.z, a0.z, b0.z); w0.w = fmaf(v0.w, a0.w, b0.w);
            w1.x = fmaf(v1.x, a1.x, b1.x); w1.y = fmaf(v1.y, a1.y, b1.y);
            w1.z = fmaf(v1.z, a1.z, b1.z); w1.w = fmaf(v1.w, a1.w, b1.w);
            w2.x = fmaf(v2.x, a2.x, b2.x); w2.y = fmaf(v2.y, a2.y, b2.y);
            w2.z = fmaf(v2.z, a2.z, b2.z); w2.w = fmaf(v2.w, a2.w, b2.w);
            w3.x = fmaf(v3.x, a3.x, b3.x); w3.y = fmaf(v3.y, a3.y, b3.y);
            w3.z = fmaf(v3.z, a3.z, b3.z); w3.w = fmaf(v3.w, a3.w, b3.w);
            float4* q = o4 + (size_t)r * FV + tid;
            __stcs(q,          w0);
            __stcs(q + FV,     w1);
            __stcs(q + 2 * FV, w2);
            __stcs(q + 3 * FV, w3);
        } else {
            for (int k = 0; k < 4; k++) {
                const int rr = r + k;
                if (rr >= n) break;
                const int dd = sd[j + k];
                float4 v = __ldcs(x4 + (size_t)rr * FV + tid);
                float4 a = __ldg(A4 + dd * FV + tid);
                float4 b = __ldg(B4 + dd * FV + tid);
                float4 w;
                w.x = fmaf(v.x, a.x, b.x); w.y = fmaf(v.y, a.y, b.y);
                w.z = fmaf(v.z, a.z, b.z); w.w = fmaf(v.w, a.w, b.w);
                __stcs(o4 + (size_t)rr * FV + tid, w);
            }
        }
    }
}

extern "C" void kernel_launch(void* const* d_in, const int* in_sizes, int n_in,
                              void* d_out, int out_size) {
    const float* x     = (const float*)d_in[0];
    const int*   y     = (const int*)d_in[1];
    const float* gamma = (const float*)d_in[2];
    const float* beta  = (const float*)d_in[3];
    float* out = (float*)d_out;

    const int n    = in_sizes[1];
    const int nseg = (n + RSB - 1) / RSB;       // 256

    stats_k<<<nseg, 256>>>((const float4*)x, y, n);
    finalize_k<<<DDOM * 32, 256>>>(gamma, beta, nseg);
    apply_k<<<(n + RA - 1) / RA, 256>>>((const float4*)x, (float4*)out, n);
}